// round 10
// baseline (speedup 1.0000x reference)
#include <cuda_runtime.h>
#include <math.h>
#include <float.h>

#define DIN   784
#define DH    512
#define DOUT  10
#define BATCH 256

#define KC    8        // k-chunks (split-K)
#define KCH   98       // DIN / KC
#define HT    32       // h per tile
#define BT    64       // batch per inner iteration
#define NBT   4        // batch iterations

#define GEMM_BLOCKS 128
#define PREP_BLOCKS 18

#define AS_SZ   (BT * KCH)
#define BPAD    36
#define B_SZ    (KCH * BPAD)
#define SMEM_FLOATS (AS_SZ + 2 * B_SZ)
#define SMEM_BYTES  (SMEM_FLOATS * 4)

#define TRI_N 55
#define NACC  75       // 55 mid + 10 amu + 10 aq

// ---------------- device scratch ----------------
__device__ __align__(16) float g_pmu[KC * BATCH * DH];
__device__ __align__(16) float g_pq [KC * BATCH * DH];
__device__ __align__(16) float g_Ws2[DOUT * DH];
__device__ __align__(16) float g_w2t[DOUT * DH];
__device__ float g_spb1[DH];
__device__ float g_spb2[DOUT];
__device__ float g_klpartA[GEMM_BLOCKS];
__device__ float g_klpartB[16];

// ---------------- packed f32x2 helpers ----------------
__device__ __forceinline__ unsigned long long pack2(float x, float y) {
    unsigned long long r;
    asm("mov.b64 %0, {%1, %2};" : "=l"(r) : "f"(x), "f"(y));
    return r;
}
__device__ __forceinline__ unsigned long long mul2(unsigned long long a, unsigned long long b) {
    unsigned long long r;
    asm("mul.rn.f32x2 %0, %1, %2;" : "=l"(r) : "l"(a), "l"(b));
    return r;
}
__device__ __forceinline__ unsigned long long fma2(unsigned long long a, unsigned long long b,
                                                   unsigned long long c) {
    unsigned long long r;
    asm("fma.rn.f32x2 %0, %1, %2, %3;" : "=l"(r) : "l"(a), "l"(b), "l"(c));
    return r;
}

// ---------------- softplus: fast poly for x < -1, exact fallback ----------------
__device__ __forceinline__ float sp_pair(float x, float& lsp) {
    if (x < -1.0f) {
        float u = __expf(x);
        float P = 1.0f + u * (-0.5f + u * (0.33333334f + u * (-0.25f +
                  u * (0.2f + u * (-0.16666667f + u * 0.14285715f)))));
        float d = P - 1.0f;
        float lp = d * (1.0f + d * (-0.5f + d * (0.33333334f + d * (-0.25f))));
        lsp = x + lp;
        return u * P;
    } else {
        float sp = logf(1.0f + expf(x));
        lsp = logf(sp);
        return sp;
    }
}
__device__ __forceinline__ float sp_only(float x) {
    if (x < -1.0f) {
        float u = __expf(x);
        float P = 1.0f + u * (-0.5f + u * (0.33333334f + u * (-0.25f +
                  u * (0.2f + u * (-0.16666667f + u * 0.14285715f)))));
        return u * P;
    }
    return logf(1.0f + expf(x));
}

// ---------------- KPREP: layer-2 prep + KL(B) partials ----------------
__global__ __launch_bounds__(256) void kprep(const float* __restrict__ b_sigma1,
                                             const float* __restrict__ w_mu2,
                                             const float* __restrict__ w_sigma2,
                                             const float* __restrict__ b_sigma2) {
    __shared__ float red[8];
    const int tid = threadIdx.x;
    const int pid = blockIdx.x;
    if (pid < 16) {
        float acc = 0.f;
        for (int i = pid * 256 + tid; i < DOUT * DH; i += 16 * 256) {
            float lsp;
            float sp = sp_pair(w_sigma2[i], lsp);
            g_Ws2[i] = sp;
            acc += sp - lsp;
            float v = w_mu2[i];
            acc += v * v;
            g_w2t[(i % DOUT) * DH + (i / DOUT)] = v;
        }
        #pragma unroll
        for (int s = 16; s; s >>= 1) acc += __shfl_xor_sync(0xffffffffu, acc, s);
        if ((tid & 31) == 0) red[tid >> 5] = acc;
        __syncthreads();
        if (tid == 0) {
            float t = 0.f;
            #pragma unroll
            for (int w = 0; w < 8; w++) t += red[w];
            g_klpartB[pid] = t;
        }
    } else if (pid == 16) {
        g_spb1[tid]       = sp_only(b_sigma1[tid]);
        g_spb1[tid + 256] = sp_only(b_sigma1[tid + 256]);
    } else {
        if (tid < DOUT) g_spb2[tid] = sp_only(b_sigma2[tid]);
    }
}

// ---------------- K1: split-K dual GEMM, 128 blocks x 512 threads ----------------
__global__ __launch_bounds__(512) void k1_gemm(const float* __restrict__ x,
                                               const float* __restrict__ w_mu1,
                                               const float* __restrict__ w_sigma1) {
    extern __shared__ float smem[];
    __shared__ float red[16];
    const int tid = threadIdx.x;
    const int id = blockIdx.x;

    float* As  = smem;
    float* B1s = smem + AS_SZ;
    float* B2s = B1s + B_SZ;

    const int bx = id & 15;
    const int kc = id >> 4;
    const int n0 = bx * HT;
    const int ks = kc * KCH;

    float klacc = 0.f;

    for (int i = tid; i < KCH * (HT / 4); i += 512) {      // 784 float4
        int r = i >> 3, c = i & 7;
        float4 v = *(const float4*)&w_mu1[(ks + r) * DH + n0 + c * 4];
        *(float4*)&B1s[r * BPAD + c * 4] = v;
        klacc += v.x * v.x + v.y * v.y + v.z * v.z + v.w * v.w;
    }
    for (int i = tid; i < HT * (KCH / 2); i += 512) {      // 1568 float2
        int h = i / 49, kp = i % 49;
        float2 v = *(const float2*)&w_sigma1[(n0 + h) * DIN + ks + kp * 2];
        float l0, l1;
        float s0 = sp_pair(v.x, l0);
        float s1 = sp_pair(v.y, l1);
        klacc += (s0 - l0) + (s1 - l1);
        B2s[(kp * 2)     * BPAD + h] = s0;
        B2s[(kp * 2 + 1) * BPAD + h] = s1;
    }
    #pragma unroll
    for (int s = 16; s; s >>= 1) klacc += __shfl_xor_sync(0xffffffffu, klacc, s);
    if ((tid & 31) == 0) red[tid >> 5] = klacc;
    __syncthreads();
    if (tid == 0) {
        float t = 0.f;
        #pragma unroll
        for (int w = 0; w < 16; w++) t += red[w];
        g_klpartA[id] = t;
    }

    const int tx = tid & 7;            // h quad
    const int ty = tid >> 3;           // batch row (0..63)

    for (int bt = 0; bt < NBT; bt++) {
        const int b0 = bt * BT;
        for (int i = tid; i < BT * (KCH / 2); i += 512) {  // 3136 float2
            int r = i / 49, kp = i % 49;
            *(float2*)&As[r * KCH + kp * 2] =
                *(const float2*)&x[(b0 + r) * DIN + ks + kp * 2];
        }
        __syncthreads();

        unsigned long long amu0 = 0ull, amu1 = 0ull, aq0 = 0ull, aq1 = 0ull;
        const float* ap = &As[ty * KCH];

        #pragma unroll 7
        for (int kk = 0; kk < KCH; kk++) {
            float a = ap[kk];
            ulonglong2 b1 = *(const ulonglong2*)&B1s[kk * BPAD + tx * 4];
            ulonglong2 b2 = *(const ulonglong2*)&B2s[kk * BPAD + tx * 4];
            unsigned long long apk = pack2(a, a);
            unsigned long long q   = mul2(apk, apk);
            amu0 = fma2(apk, b1.x, amu0);
            amu1 = fma2(apk, b1.y, amu1);
            aq0  = fma2(q,   b2.x, aq0);
            aq1  = fma2(q,   b2.y, aq1);
        }

        {
            int b = b0 + ty;
            ulonglong2 m; m.x = amu0; m.y = amu1;
            ulonglong2 q; q.x = aq0;  q.y = aq1;
            *(ulonglong2*)&g_pmu[(kc * BATCH + b) * DH + n0 + tx * 4] = m;
            *(ulonglong2*)&g_pq [(kc * BATCH + b) * DH + n0 + tx * 4] = q;
        }
        __syncthreads();
    }
}

// ---------------- s2 recompute from partials (cross-batch trace gather) ----------------
__device__ __forceinline__ float s2_at(int m, int h, const float* __restrict__ b_mu1) {
    float mu = b_mu1[h];
    #pragma unroll
    for (int c = 0; c < KC; c++) mu += g_pmu[(c * BATCH + m) * DH + h];
    if (mu <= 0.f) return 0.f;
    float q = g_spb1[h];
    #pragma unroll
    for (int c = 0; c < KC; c++) q += g_pq[(c * BATCH + m) * DH + h];
    return q;
}

// ---------------- per-warp accumulator strip over a 128-h quarter, float2 ----------------
// acc index space: 0..54 = mid (upper-tri o<=p), 55..64 = amu[o], 65..74 = aq[o]
template<int LO, int HI>
__device__ __forceinline__ void accum_strip(const float* __restrict__ m2s,
                                            const float* __restrict__ s2s,
                                            const float* __restrict__ w2s,
                                            float* __restrict__ wp,
                                            int h0, int lane) {
    float acc[HI - LO];
    #pragma unroll
    for (int j = 0; j < HI - LO; j++) acc[j] = 0.f;

    #pragma unroll
    for (int t = 0; t < 2; t++) {                 // 2 x 64 = 128 h (one quarter)
        int h = h0 + t * 64 + lane * 2;
        float2 m = *(const float2*)&m2s[h];
        float2 s = *(const float2*)&s2s[h];
        float2 mm = make_float2(m.x * m.x, m.y * m.y);
        float2 w[DOUT], sw[DOUT];
        #pragma unroll
        for (int o = 0; o < DOUT; o++) w[o] = *(const float2*)&w2s[o * DH + h];
        #pragma unroll
        for (int o = 0; o < DOUT; o++) {
            sw[o].x = s.x * w[o].x;
            sw[o].y = s.y * w[o].y;
        }
        {
            int e = 0;
            #pragma unroll
            for (int o = 0; o < DOUT; o++)
                #pragma unroll
                for (int p = o; p < DOUT; p++) {
                    if (e >= LO && e < HI)
                        acc[e - LO] += w[p].x * sw[o].x + w[p].y * sw[o].y;
                    e++;
                }
        }
        #pragma unroll
        for (int o = 0; o < DOUT; o++)
            if (TRI_N + o >= LO && TRI_N + o < HI)
                acc[TRI_N + o - LO] += w[o].x * m.x + w[o].y * m.y;
        #pragma unroll
        for (int o = 0; o < DOUT; o++)
            if (65 + o >= LO && 65 + o < HI) {
                float2 ws = __ldg((const float2*)&g_Ws2[o * DH + h]);
                acc[65 + o - LO] += ws.x * mm.x + ws.y * mm.y;
            }
    }

    #pragma unroll
    for (int s = 16; s; s >>= 1)
        #pragma unroll
        for (int j = 0; j < HI - LO; j++)
            acc[j] += __shfl_xor_sync(0xffffffffu, acc[j], s);

    #pragma unroll
    for (int j = 0; j < HI - LO; j++)
        if (lane == j) wp[LO + j] = acc[j];
}

// ---------------- K2: one block per batch, 512 threads (4 strips x 4 quarters) ----------------
__global__ __launch_bounds__(512) void k2_layer2(const float* __restrict__ b_mu1,
                                                 const float* __restrict__ b_mu2,
                                                 float* __restrict__ out) {
    __shared__ float m2s[DH], s2s[DH];
    __shared__ float w2s[DOUT * DH];            // 20KB
    __shared__ float wp[4][NACC];
    __shared__ float S[240];
    __shared__ float saq[DOUT];

    const int tid = threadIdx.x;
    const int warp = tid >> 5, lane = tid & 31;
    const int b = blockIdx.x;
    const int SZ = BATCH * DH;

    // ---- phase 1: combine split-K partials + bias + ReLU (1 h per thread) ----
    {
        int h = tid;
        int idx = b * DH + h;
        float mu = __ldg(b_mu1 + h);
        #pragma unroll
        for (int c = 0; c < KC; c++) mu += g_pmu[c * SZ + idx];
        float q = g_spb1[h];
        #pragma unroll
        for (int c = 0; c < KC; c++) q += g_pq[c * SZ + idx];
        bool gate = (mu > 0.f);
        m2s[h] = gate ? mu : 0.f;
        s2s[h] = gate ? q : 0.f;
    }
    for (int i = tid; i < DOUT * DH / 4; i += 512)
        *(float4*)&w2s[i * 4] = *(const float4*)&g_w2t[i * 4];
    __syncthreads();

    // ---- phase 2: 16 warps = 4 accumulator strips x 4 h-quarters ----
    {
        const int quarter = warp >> 2;
        const int h0 = quarter * 128;
        float* wpp = wp[quarter];
        switch (warp & 3) {
            case 0: accum_strip< 0, 19>(m2s, s2s, w2s, wpp, h0, lane); break;
            case 1: accum_strip<19, 38>(m2s, s2s, w2s, wpp, h0, lane); break;
            case 2: accum_strip<38, 57>(m2s, s2s, w2s, wpp, h0, lane); break;
            default: accum_strip<57, 75>(m2s, s2s, w2s, wpp, h0, lane); break;
        }
    }
    __syncthreads();

    // ---- assembly ----
    if (tid < NACC) {
        float v = (wp[0][tid] + wp[1][tid]) + (wp[2][tid] + wp[3][tid]);
        if (tid < TRI_N) {
            int o = 0, rem = tid;
            #pragma unroll
            for (int r = 0; r < DOUT; r++) {
                if (rem >= DOUT - r && o == r) { rem -= DOUT - r; o = r + 1; }
            }
            int p = o + rem;
            S[o * DOUT + p] = v;
            S[p * DOUT + o] = v;
        } else if (tid < 65) {
            int o = tid - TRI_N;
            S[210 + o] = v + __ldg(b_mu2 + o);
        } else {
            saq[tid - 65] = v;
        }
    }
    __syncthreads();
    if (tid < DOUT) {
        // faithful replication of reference's flattened-view trace term
        int n  = DOUT * b + tid;
        int qn = n >> 8;
        int mn = n & 255;
        float trf = g_Ws2[qn * DH + 2 * mn]     * s2_at(mn, mn, b_mu1)
                  + g_Ws2[qn * DH + 2 * mn + 1] * s2_at(mn, 256 + mn, b_mu1);
        S[tid * DOUT + tid] += trf + saq[tid] + g_spb2[tid];
    }
    __syncthreads();

    // ---- softmax + sandwich (warp 0) ----
    if (warp == 0) {
        float v = (lane < DOUT) ? S[210 + lane] : -FLT_MAX;
        float mx = v;
        #pragma unroll
        for (int s = 16; s; s >>= 1) mx = fmaxf(mx, __shfl_xor_sync(0xffffffffu, mx, s));
        float e = (lane < DOUT) ? expf(v - mx) : 0.f;
        float sm = e;
        #pragma unroll
        for (int s = 16; s; s >>= 1) sm += __shfl_xor_sync(0xffffffffu, sm, s);
        if (lane < DOUT) {
            float p = e / sm;
            S[200 + lane] = p;
            out[b * DOUT + lane] = p;
        }
        __syncwarp();

        if (lane < DOUT) {
            float a = 0.f;
            #pragma unroll
            for (int j = 0; j < DOUT; j++) a += S[200 + j] * S[j * DOUT + lane];
            S[220 + lane] = a;
        }
        __syncwarp();
        for (int e2 = lane; e2 < DOUT * DOUT; e2 += 32) {
            int i = e2 / DOUT, k = e2 % DOUT;
            S[100 + e2] = S[200 + i] * (S[e2] - S[220 + k]);
        }
        __syncwarp();
        if (lane < DOUT) {
            float a = 0.f;
            #pragma unroll
            for (int k = 0; k < DOUT; k++) a += S[100 + lane * DOUT + k] * S[200 + k];
            S[230 + lane] = a;
        }
        __syncwarp();
        for (int e2 = lane; e2 < DOUT * DOUT; e2 += 32) {
            int i = e2 / DOUT, l = e2 % DOUT;
            out[BATCH * DOUT + b * DOUT * DOUT + e2] = S[200 + l] * (S[100 + e2] - S[230 + i]);
        }
    }
}

// ---------------- K3: KL finalize ----------------
__global__ __launch_bounds__(128) void k3_fin(float* __restrict__ out) {
    __shared__ float kred[4];
    const int tid = threadIdx.x;
    float a = g_klpartA[tid];
    if (tid < 16) a += g_klpartB[tid];
    #pragma unroll
    for (int s = 16; s; s >>= 1) a += __shfl_xor_sync(0xffffffffu, a, s);
    if ((tid & 31) == 0) kred[tid >> 5] = a;
    __syncthreads();
    if (tid == 0)
        out[BATCH * DOUT + BATCH * DOUT * DOUT] =
            0.5f * ((kred[0] + kred[1] + kred[2] + kred[3])
                    - (float)(DH * DIN + DOUT * DH));
}

// ---------------- launch ----------------
extern "C" void kernel_launch(void* const* d_in, const int* in_sizes, int n_in,
                              void* d_out, int out_size) {
    const float* x        = (const float*)d_in[0];
    const float* w_mu1    = (const float*)d_in[1];
    const float* w_sigma1 = (const float*)d_in[2];
    const float* b_mu1    = (const float*)d_in[3];
    const float* b_sigma1 = (const float*)d_in[4];
    const float* w_mu2    = (const float*)d_in[5];
    const float* w_sigma2 = (const float*)d_in[6];
    const float* b_mu2    = (const float*)d_in[7];
    const float* b_sigma2 = (const float*)d_in[8];
    float* out = (float*)d_out;

    cudaFuncSetAttribute(k1_gemm, cudaFuncAttributeMaxDynamicSharedMemorySize, SMEM_BYTES);
    kprep<<<PREP_BLOCKS, 256>>>(b_sigma1, w_mu2, w_sigma2, b_sigma2);
    k1_gemm<<<GEMM_BLOCKS, 512, SMEM_BYTES>>>(x, w_mu1, w_sigma1);
    k2_layer2<<<BATCH, 512>>>(b_mu1, b_mu2, out);
    k3_fin<<<1, 128>>>(out);
}

// round 11
// speedup vs baseline: 1.3802x; 1.3802x over previous
#include <cuda_runtime.h>
#include <math.h>
#include <float.h>

#define DIN   784
#define DH    512
#define DOUT  10
#define BATCH 256

#define KC    4        // k-chunks (split-K)
#define KCH   196      // DIN / KC

#define GEMM_BLOCKS 128
#define PREP_BLOCKS 18
#define TOTAL_BLOCKS (GEMM_BLOCKS + PREP_BLOCKS)

#define AS_SZ  (64 * KCH)       // 12544 floats, natural [b][k]
#define BPAD   68
#define B_SZ   (KCH * BPAD)     // 13328 floats, [k][h]
#define SMEM_FLOATS (AS_SZ + 2 * B_SZ)
#define SMEM_BYTES  (SMEM_FLOATS * 4)   // 156800

#define TRI_N 55
#define NACC  75       // 55 mid + 10 amu + 10 aq

// ---------------- device scratch ----------------
__device__ __align__(16) float g_pmu[KC * BATCH * DH];
__device__ __align__(16) float g_pq [KC * BATCH * DH];
__device__ __align__(16) float g_Ws2[DOUT * DH];
__device__ __align__(16) float g_w2t[DOUT * DH];
__device__ float g_spb1[DH];
__device__ float g_spb2[DOUT];
__device__ float g_klpartA[32];
__device__ float g_klpartB[16];

// ---------------- packed f32x2 helpers ----------------
__device__ __forceinline__ unsigned long long pack2(float x, float y) {
    unsigned long long r;
    asm("mov.b64 %0, {%1, %2};" : "=l"(r) : "f"(x), "f"(y));
    return r;
}
__device__ __forceinline__ unsigned long long mul2(unsigned long long a, unsigned long long b) {
    unsigned long long r;
    asm("mul.rn.f32x2 %0, %1, %2;" : "=l"(r) : "l"(a), "l"(b));
    return r;
}
__device__ __forceinline__ unsigned long long fma2(unsigned long long a, unsigned long long b,
                                                   unsigned long long c) {
    unsigned long long r;
    asm("fma.rn.f32x2 %0, %1, %2, %3;" : "=l"(r) : "l"(a), "l"(b), "l"(c));
    return r;
}

// ---------------- softplus: fast poly for x < -1, exact fallback ----------------
__device__ __forceinline__ float sp_pair(float x, float& lsp) {
    if (x < -1.0f) {
        float u = __expf(x);
        float P = 1.0f + u * (-0.5f + u * (0.33333334f + u * (-0.25f +
                  u * (0.2f + u * (-0.16666667f + u * 0.14285715f)))));
        float d = P - 1.0f;
        float lp = d * (1.0f + d * (-0.5f + d * (0.33333334f + d * (-0.25f))));
        lsp = x + lp;
        return u * P;
    } else {
        float sp = logf(1.0f + expf(x));
        lsp = logf(sp);
        return sp;
    }
}
__device__ __forceinline__ float sp_only(float x) {
    if (x < -1.0f) {
        float u = __expf(x);
        float P = 1.0f + u * (-0.5f + u * (0.33333334f + u * (-0.25f +
                  u * (0.2f + u * (-0.16666667f + u * 0.14285715f)))));
        return u * P;
    }
    return logf(1.0f + expf(x));
}

// ---------------- K1 MEGA: 128 GEMM blocks (64b x 64h x 196k) + 18 prep, one wave ----------------
__global__ __launch_bounds__(256) void k1_mega(const float* __restrict__ x,
                                               const float* __restrict__ w_mu1,
                                               const float* __restrict__ w_sigma1,
                                               const float* __restrict__ b_sigma1,
                                               const float* __restrict__ w_mu2,
                                               const float* __restrict__ w_sigma2,
                                               const float* __restrict__ b_sigma2) {
    extern __shared__ float smem[];
    __shared__ float red[8];
    const int tid = threadIdx.x;
    const int id = blockIdx.x;

    if (id >= GEMM_BLOCKS) {
        // ---- prep role ----
        const int pid = id - GEMM_BLOCKS;
        if (pid < 16) {
            float acc = 0.f;
            for (int i = pid * 256 + tid; i < DOUT * DH; i += 16 * 256) {
                float lsp;
                float sp = sp_pair(w_sigma2[i], lsp);
                g_Ws2[i] = sp;
                acc += sp - lsp;
                float v = w_mu2[i];
                acc += v * v;
                g_w2t[(i % DOUT) * DH + (i / DOUT)] = v;
            }
            #pragma unroll
            for (int s = 16; s; s >>= 1) acc += __shfl_xor_sync(0xffffffffu, acc, s);
            if ((tid & 31) == 0) red[tid >> 5] = acc;
            __syncthreads();
            if (tid == 0) {
                float t = 0.f;
                #pragma unroll
                for (int w = 0; w < 8; w++) t += red[w];
                g_klpartB[pid] = t;
            }
        } else if (pid == 16) {
            g_spb1[tid]       = sp_only(b_sigma1[tid]);
            g_spb1[tid + 256] = sp_only(b_sigma1[tid + 256]);
        } else {
            if (tid < DOUT) g_spb2[tid] = sp_only(b_sigma2[tid]);
        }
        return;
    }

    // ---- GEMM role ----
    float* As  = smem;              // [b][k] natural, 64 x 196
    float* B1s = smem + AS_SZ;      // [k][h], 196 x 68
    float* B2s = B1s + B_SZ;        // [k][h] softplus'd

    const int ht = id >> 4;
    const int bt = (id & 15) & 3;
    const int kc = (id & 15) >> 2;
    const int n0 = ht * 64;
    const int b0 = bt * 64;
    const int ks = kc * KCH;
    const bool do_kl = (bt == 0);

    float klacc = 0.f;

    // A: x[b][k] natural layout, coalesced float4 along k
    for (int i = tid; i < 64 * 49; i += 256) {
        int r = i / 49, c = i % 49;
        *(float4*)&As[r * KCH + c * 4] =
            *(const float4*)&x[(b0 + r) * DIN + ks + c * 4];
    }
    // B1: w_mu1[k][h] natural, coalesced; fold sum-of-squares
    for (int i = tid; i < KCH * 16; i += 256) {
        int r = i >> 4, c = i & 15;
        float4 v = *(const float4*)&w_mu1[(ks + r) * DH + n0 + c * 4];
        *(float4*)&B1s[r * BPAD + c * 4] = v;
        if (do_kl) klacc += v.x * v.x + v.y * v.y + v.z * v.z + v.w * v.w;
    }
    // B2: softplus(w_sigma1[h][k]) transposed into [k][h]; conflict-free stores
    // (lanes span consecutive h for fixed k-quad)
    for (int i = tid; i < 64 * 49; i += 256) {
        int r = i & 63, c = i >> 6;               // r = h index, c = k quad
        float4 v = *(const float4*)&w_sigma1[(n0 + r) * DIN + ks + c * 4];
        float l0, l1, l2, l3;
        float s0 = sp_pair(v.x, l0);
        float s1 = sp_pair(v.y, l1);
        float s2 = sp_pair(v.z, l2);
        float s3 = sp_pair(v.w, l3);
        if (do_kl) klacc += (s0 - l0) + (s1 - l1) + (s2 - l2) + (s3 - l3);
        B2s[(c * 4 + 0) * BPAD + r] = s0;
        B2s[(c * 4 + 1) * BPAD + r] = s1;
        B2s[(c * 4 + 2) * BPAD + r] = s2;
        B2s[(c * 4 + 3) * BPAD + r] = s3;
    }
    if (do_kl) {
        #pragma unroll
        for (int s = 16; s; s >>= 1) klacc += __shfl_xor_sync(0xffffffffu, klacc, s);
        if ((tid & 31) == 0) red[tid >> 5] = klacc;
    }
    __syncthreads();
    if (do_kl && tid == 0) {
        float t = 0.f;
        #pragma unroll
        for (int w = 0; w < 8; w++) t += red[w];
        g_klpartA[ht * 4 + kc] = t;
    }

    // ---- compute: 4b x 4h microtile, f32x2, 196 straight kk ----
    const int tx = tid & 15;            // h quad (x4 = 64 h)
    const int ty = tid >> 4;            // b quad (x4 = 64 b)

    unsigned long long mu[4][2], qq[4][2];
    #pragma unroll
    for (int r = 0; r < 4; r++) {
        mu[r][0] = mu[r][1] = 0ull;
        qq[r][0] = qq[r][1] = 0ull;
    }

    const float* ap = &As[(ty * 4) * KCH];

    #pragma unroll 4
    for (int kk = 0; kk < KCH; kk++) {
        float a0 = ap[kk];
        float a1 = ap[KCH + kk];
        float a2 = ap[2 * KCH + kk];
        float a3 = ap[3 * KCH + kk];
        ulonglong2 b1 = *(const ulonglong2*)&B1s[kk * BPAD + tx * 4];
        ulonglong2 b2 = *(const ulonglong2*)&B2s[kk * BPAD + tx * 4];
        unsigned long long p0 = pack2(a0, a0);
        unsigned long long p1 = pack2(a1, a1);
        unsigned long long p2 = pack2(a2, a2);
        unsigned long long p3 = pack2(a3, a3);
        unsigned long long s0 = mul2(p0, p0);
        unsigned long long s1 = mul2(p1, p1);
        unsigned long long s2 = mul2(p2, p2);
        unsigned long long s3 = mul2(p3, p3);
        mu[0][0] = fma2(p0, b1.x, mu[0][0]); mu[0][1] = fma2(p0, b1.y, mu[0][1]);
        mu[1][0] = fma2(p1, b1.x, mu[1][0]); mu[1][1] = fma2(p1, b1.y, mu[1][1]);
        mu[2][0] = fma2(p2, b1.x, mu[2][0]); mu[2][1] = fma2(p2, b1.y, mu[2][1]);
        mu[3][0] = fma2(p3, b1.x, mu[3][0]); mu[3][1] = fma2(p3, b1.y, mu[3][1]);
        qq[0][0] = fma2(s0, b2.x, qq[0][0]); qq[0][1] = fma2(s0, b2.y, qq[0][1]);
        qq[1][0] = fma2(s1, b2.x, qq[1][0]); qq[1][1] = fma2(s1, b2.y, qq[1][1]);
        qq[2][0] = fma2(s2, b2.x, qq[2][0]); qq[2][1] = fma2(s2, b2.y, qq[2][1]);
        qq[3][0] = fma2(s3, b2.x, qq[3][0]); qq[3][1] = fma2(s3, b2.y, qq[3][1]);
    }

    // ---- epilogue: split-K partials ----
    #pragma unroll
    for (int r = 0; r < 4; r++) {
        int b = b0 + ty * 4 + r;
        ulonglong2 m; m.x = mu[r][0]; m.y = mu[r][1];
        ulonglong2 q; q.x = qq[r][0]; q.y = qq[r][1];
        *(ulonglong2*)&g_pmu[(kc * BATCH + b) * DH + n0 + tx * 4] = m;
        *(ulonglong2*)&g_pq [(kc * BATCH + b) * DH + n0 + tx * 4] = q;
    }
}

// ---------------- s2 recompute from partials (cross-batch trace gather) ----------------
__device__ __forceinline__ float s2_at(int m, int h, const float* __restrict__ b_mu1) {
    float mu = b_mu1[h];
    #pragma unroll
    for (int c = 0; c < KC; c++) mu += g_pmu[(c * BATCH + m) * DH + h];
    if (mu <= 0.f) return 0.f;
    float q = g_spb1[h];
    #pragma unroll
    for (int c = 0; c < KC; c++) q += g_pq[(c * BATCH + m) * DH + h];
    return q;
}

// ---------------- per-warp accumulator strip over a 128-h quarter, float2 ----------------
template<int LO, int HI>
__device__ __forceinline__ void accum_strip(const float* __restrict__ m2s,
                                            const float* __restrict__ s2s,
                                            const float* __restrict__ w2s,
                                            float* __restrict__ wp,
                                            int h0, int lane) {
    float acc[HI - LO];
    #pragma unroll
    for (int j = 0; j < HI - LO; j++) acc[j] = 0.f;

    #pragma unroll
    for (int t = 0; t < 2; t++) {
        int h = h0 + t * 64 + lane * 2;
        float2 m = *(const float2*)&m2s[h];
        float2 s = *(const float2*)&s2s[h];
        float2 mm = make_float2(m.x * m.x, m.y * m.y);
        float2 w[DOUT], sw[DOUT];
        #pragma unroll
        for (int o = 0; o < DOUT; o++) w[o] = *(const float2*)&w2s[o * DH + h];
        #pragma unroll
        for (int o = 0; o < DOUT; o++) {
            sw[o].x = s.x * w[o].x;
            sw[o].y = s.y * w[o].y;
        }
        {
            int e = 0;
            #pragma unroll
            for (int o = 0; o < DOUT; o++)
                #pragma unroll
                for (int p = o; p < DOUT; p++) {
                    if (e >= LO && e < HI)
                        acc[e - LO] += w[p].x * sw[o].x + w[p].y * sw[o].y;
                    e++;
                }
        }
        #pragma unroll
        for (int o = 0; o < DOUT; o++)
            if (TRI_N + o >= LO && TRI_N + o < HI)
                acc[TRI_N + o - LO] += w[o].x * m.x + w[o].y * m.y;
        #pragma unroll
        for (int o = 0; o < DOUT; o++)
            if (65 + o >= LO && 65 + o < HI) {
                float2 ws = __ldg((const float2*)&g_Ws2[o * DH + h]);
                acc[65 + o - LO] += ws.x * mm.x + ws.y * mm.y;
            }
    }

    #pragma unroll
    for (int s = 16; s; s >>= 1)
        #pragma unroll
        for (int j = 0; j < HI - LO; j++)
            acc[j] += __shfl_xor_sync(0xffffffffu, acc[j], s);

    #pragma unroll
    for (int j = 0; j < HI - LO; j++)
        if (lane == j) wp[LO + j] = acc[j];
}

// ---------------- K2: one block per batch, 512 threads + KL finalize ----------------
__global__ __launch_bounds__(512) void k2_layer2(const float* __restrict__ b_mu1,
                                                 const float* __restrict__ b_mu2,
                                                 float* __restrict__ out) {
    __shared__ float m2s[DH], s2s[DH];
    __shared__ float w2s[DOUT * DH];
    __shared__ float wp[4][NACC];
    __shared__ float S[240];
    __shared__ float saq[DOUT];

    const int tid = threadIdx.x;
    const int warp = tid >> 5, lane = tid & 31;
    const int b = blockIdx.x;
    const int SZ = BATCH * DH;

    // ---- phase 1: combine split-K partials + bias + ReLU (1 h per thread) ----
    {
        int h = tid;
        int idx = b * DH + h;
        float mu = __ldg(b_mu1 + h);
        #pragma unroll
        for (int c = 0; c < KC; c++) mu += g_pmu[c * SZ + idx];
        float q = g_spb1[h];
        #pragma unroll
        for (int c = 0; c < KC; c++) q += g_pq[c * SZ + idx];
        bool gate = (mu > 0.f);
        m2s[h] = gate ? mu : 0.f;
        s2s[h] = gate ? q : 0.f;
    }
    for (int i = tid; i < DOUT * DH / 4; i += 512)
        *(float4*)&w2s[i * 4] = *(const float4*)&g_w2t[i * 4];
    __syncthreads();

    // ---- phase 2: 16 warps = 4 accumulator strips x 4 h-quarters ----
    {
        const int quarter = warp >> 2;
        const int h0 = quarter * 128;
        float* wpp = wp[quarter];
        switch (warp & 3) {
            case 0: accum_strip< 0, 19>(m2s, s2s, w2s, wpp, h0, lane); break;
            case 1: accum_strip<19, 38>(m2s, s2s, w2s, wpp, h0, lane); break;
            case 2: accum_strip<38, 57>(m2s, s2s, w2s, wpp, h0, lane); break;
            default: accum_strip<57, 75>(m2s, s2s, w2s, wpp, h0, lane); break;
        }
    }
    __syncthreads();

    // ---- assembly ----
    if (tid < NACC) {
        float v = (wp[0][tid] + wp[1][tid]) + (wp[2][tid] + wp[3][tid]);
        if (tid < TRI_N) {
            int o = 0, rem = tid;
            #pragma unroll
            for (int r = 0; r < DOUT; r++) {
                if (rem >= DOUT - r && o == r) { rem -= DOUT - r; o = r + 1; }
            }
            int p = o + rem;
            S[o * DOUT + p] = v;
            S[p * DOUT + o] = v;
        } else if (tid < 65) {
            int o = tid - TRI_N;
            S[210 + o] = v + __ldg(b_mu2 + o);
        } else {
            saq[tid - 65] = v;
        }
    }
    __syncthreads();
    if (tid < DOUT) {
        // faithful replication of reference's flattened-view trace term
        int n  = DOUT * b + tid;
        int qn = n >> 8;
        int mn = n & 255;
        float trf = g_Ws2[qn * DH + 2 * mn]     * s2_at(mn, mn, b_mu1)
                  + g_Ws2[qn * DH + 2 * mn + 1] * s2_at(mn, 256 + mn, b_mu1);
        S[tid * DOUT + tid] += trf + saq[tid] + g_spb2[tid];
    }
    __syncthreads();

    // ---- softmax + sandwich (warp 0) ----
    if (warp == 0) {
        float v = (lane < DOUT) ? S[210 + lane] : -FLT_MAX;
        float mx = v;
        #pragma unroll
        for (int s = 16; s; s >>= 1) mx = fmaxf(mx, __shfl_xor_sync(0xffffffffu, mx, s));
        float e = (lane < DOUT) ? expf(v - mx) : 0.f;
        float sm = e;
        #pragma unroll
        for (int s = 16; s; s >>= 1) sm += __shfl_xor_sync(0xffffffffu, sm, s);
        if (lane < DOUT) {
            float p = e / sm;
            S[200 + lane] = p;
            out[b * DOUT + lane] = p;
        }
        __syncwarp();

        if (lane < DOUT) {
            float a = 0.f;
            #pragma unroll
            for (int j = 0; j < DOUT; j++) a += S[200 + j] * S[j * DOUT + lane];
            S[220 + lane] = a;
        }
        __syncwarp();
        for (int e2 = lane; e2 < DOUT * DOUT; e2 += 32) {
            int i = e2 / DOUT, k = e2 % DOUT;
            S[100 + e2] = S[200 + i] * (S[e2] - S[220 + k]);
        }
        __syncwarp();
        if (lane < DOUT) {
            float a = 0.f;
            #pragma unroll
            for (int k = 0; k < DOUT; k++) a += S[100 + lane * DOUT + k] * S[200 + k];
            S[230 + lane] = a;
        }
        __syncwarp();
        for (int e2 = lane; e2 < DOUT * DOUT; e2 += 32) {
            int i = e2 / DOUT, l = e2 % DOUT;
            out[BATCH * DOUT + b * DOUT * DOUT + e2] = S[200 + l] * (S[100 + e2] - S[230 + i]);
        }

        // ---- KL finalize (block 0, warp 0) ----
        if (b == 0) {
            float a = (lane < 32) ? g_klpartA[lane] : 0.f;
            if (lane < 16) a += g_klpartB[lane];
            #pragma unroll
            for (int s = 16; s; s >>= 1) a += __shfl_xor_sync(0xffffffffu, a, s);
            if (lane == 0)
                out[BATCH * DOUT + BATCH * DOUT * DOUT] =
                    0.5f * (a - (float)(DH * DIN + DOUT * DH));
        }
    }
}

// ---------------- launch ----------------
extern "C" void kernel_launch(void* const* d_in, const int* in_sizes, int n_in,
                              void* d_out, int out_size) {
    const float* x        = (const float*)d_in[0];
    const float* w_mu1    = (const float*)d_in[1];
    const float* w_sigma1 = (const float*)d_in[2];
    const float* b_mu1    = (const float*)d_in[3];
    const float* b_sigma1 = (const float*)d_in[4];
    const float* w_mu2    = (const float*)d_in[5];
    const float* w_sigma2 = (const float*)d_in[6];
    const float* b_mu2    = (const float*)d_in[7];
    const float* b_sigma2 = (const float*)d_in[8];
    float* out = (float*)d_out;

    cudaFuncSetAttribute(k1_mega, cudaFuncAttributeMaxDynamicSharedMemorySize, SMEM_BYTES);
    k1_mega<<<TOTAL_BLOCKS, 256, SMEM_BYTES>>>(x, w_mu1, w_sigma1, b_sigma1,
                                               w_mu2, w_sigma2, b_sigma2);
    k2_layer2<<<BATCH, 512>>>(b_mu1, b_mu2, out);
}

// round 12
// speedup vs baseline: 1.4161x; 1.0260x over previous
#include <cuda_runtime.h>
#include <math.h>
#include <float.h>

#define DIN   784
#define DH    512
#define DOUT  10
#define BATCH 256

#define KC    4        // k-chunks (split-K)
#define KCH   196      // DIN / KC

#define GEMM_BLOCKS 256
#define PREP_BLOCKS 18
#define TOTAL_BLOCKS (GEMM_BLOCKS + PREP_BLOCKS)

#define AS_SZ  (64 * KCH)       // 12544 floats, natural [b][k]
#define BPAD   36
#define B_SZ   (KCH * BPAD)     // 7056 floats, [k][h] (32h + pad)
#define SMEM_FLOATS (AS_SZ + 2 * B_SZ)      // 26656
#define SMEM_BYTES  (SMEM_FLOATS * 4)       // 106624 -> 2 blocks/SM

#define TRI_N 55
#define NACC  75       // 55 mid + 10 amu + 10 aq

// ---------------- device scratch ----------------
__device__ __align__(16) float g_pmu[KC * BATCH * DH];
__device__ __align__(16) float g_pq [KC * BATCH * DH];
__device__ __align__(16) float g_Ws2[DOUT * DH];
__device__ __align__(16) float g_w2t[DOUT * DH];
__device__ float g_spb1[DH];
__device__ float g_spb2[DOUT];
__device__ float g_klpartA[64];
__device__ float g_klpartB[16];

// ---------------- softplus: fast poly for x < -1, exact fallback ----------------
__device__ __forceinline__ float sp_pair(float x, float& lsp) {
    if (x < -1.0f) {
        float u = __expf(x);
        float P = 1.0f + u * (-0.5f + u * (0.33333334f + u * (-0.25f +
                  u * (0.2f + u * (-0.16666667f + u * 0.14285715f)))));
        float d = P - 1.0f;
        float lp = d * (1.0f + d * (-0.5f + d * (0.33333334f + d * (-0.25f))));
        lsp = x + lp;
        return u * P;
    } else {
        float sp = logf(1.0f + expf(x));
        lsp = logf(sp);
        return sp;
    }
}
__device__ __forceinline__ float sp_only(float x) {
    if (x < -1.0f) {
        float u = __expf(x);
        float P = 1.0f + u * (-0.5f + u * (0.33333334f + u * (-0.25f +
                  u * (0.2f + u * (-0.16666667f + u * 0.14285715f)))));
        return u * P;
    }
    return logf(1.0f + expf(x));
}

// ---------------- K1 MEGA: 256 GEMM blocks (64b x 32h x 196k, 2/SM) + 18 prep ----------------
__global__ __launch_bounds__(256) void k1_mega(const float* __restrict__ x,
                                               const float* __restrict__ w_mu1,
                                               const float* __restrict__ w_sigma1,
                                               const float* __restrict__ b_sigma1,
                                               const float* __restrict__ w_mu2,
                                               const float* __restrict__ w_sigma2,
                                               const float* __restrict__ b_sigma2) {
    extern __shared__ float smem[];
    __shared__ float red[8];
    const int tid = threadIdx.x;
    const int id = blockIdx.x;

    if (id >= GEMM_BLOCKS) {
        // ---- prep role ----
        const int pid = id - GEMM_BLOCKS;
        if (pid < 16) {
            float acc = 0.f;
            for (int i = pid * 256 + tid; i < DOUT * DH; i += 16 * 256) {
                float lsp;
                float sp = sp_pair(w_sigma2[i], lsp);
                g_Ws2[i] = sp;
                acc += sp - lsp;
                float v = w_mu2[i];
                acc += v * v;
                g_w2t[(i % DOUT) * DH + (i / DOUT)] = v;
            }
            #pragma unroll
            for (int s = 16; s; s >>= 1) acc += __shfl_xor_sync(0xffffffffu, acc, s);
            if ((tid & 31) == 0) red[tid >> 5] = acc;
            __syncthreads();
            if (tid == 0) {
                float t = 0.f;
                #pragma unroll
                for (int w = 0; w < 8; w++) t += red[w];
                g_klpartB[pid] = t;
            }
        } else if (pid == 16) {
            g_spb1[tid]       = sp_only(b_sigma1[tid]);
            g_spb1[tid + 256] = sp_only(b_sigma1[tid + 256]);
        } else {
            if (tid < DOUT) g_spb2[tid] = sp_only(b_sigma2[tid]);
        }
        return;
    }

    // ---- GEMM role ----
    float* As  = smem;              // [b][k] natural, 64 x 196
    float* B1s = smem + AS_SZ;      // [k][h], 196 x 36 (32h used)
    float* B2s = B1s + B_SZ;        // [k][h] softplus'd

    const int ht = id >> 4;                 // 0..15
    const int bt = (id >> 2) & 3;           // 0..3
    const int kc = id & 3;                  // 0..3
    const int n0 = ht * 32;
    const int b0 = bt * 64;
    const int ks = kc * KCH;
    const bool do_kl = (bt == 0);

    float klacc = 0.f;

    // A: x[b][k] natural, coalesced float4 along k (64 x 49 quads)
    for (int i = tid; i < 64 * 49; i += 256) {
        int r = i / 49, c = i % 49;
        *(float4*)&As[r * KCH + c * 4] =
            *(const float4*)&x[(b0 + r) * DIN + ks + c * 4];
    }
    // B1: w_mu1[k][h] natural, coalesced (196 x 8 quads); fold sum-of-squares
    for (int i = tid; i < KCH * 8; i += 256) {
        int r = i >> 3, c = i & 7;
        float4 v = *(const float4*)&w_mu1[(ks + r) * DH + n0 + c * 4];
        *(float4*)&B1s[r * BPAD + c * 4] = v;
        if (do_kl) klacc += v.x * v.x + v.y * v.y + v.z * v.z + v.w * v.w;
    }
    // B2: softplus(w_sigma1[h][k]) transposed into [k][h] (32h x 49 quads)
    for (int i = tid; i < 32 * 49; i += 256) {
        int h = i & 31, kq = i >> 5;
        float4 v = *(const float4*)&w_sigma1[(n0 + h) * DIN + ks + kq * 4];
        float l0, l1, l2, l3;
        float s0 = sp_pair(v.x, l0);
        float s1 = sp_pair(v.y, l1);
        float s2 = sp_pair(v.z, l2);
        float s3 = sp_pair(v.w, l3);
        if (do_kl) klacc += (s0 - l0) + (s1 - l1) + (s2 - l2) + (s3 - l3);
        B2s[(kq * 4 + 0) * BPAD + h] = s0;
        B2s[(kq * 4 + 1) * BPAD + h] = s1;
        B2s[(kq * 4 + 2) * BPAD + h] = s2;
        B2s[(kq * 4 + 3) * BPAD + h] = s3;
    }
    if (do_kl) {
        #pragma unroll
        for (int s = 16; s; s >>= 1) klacc += __shfl_xor_sync(0xffffffffu, klacc, s);
        if ((tid & 31) == 0) red[tid >> 5] = klacc;
    }
    __syncthreads();
    if (do_kl && tid == 0) {
        float t = 0.f;
        #pragma unroll
        for (int w = 0; w < 8; w++) t += red[w];
        g_klpartA[ht * 4 + kc] = t;
    }

    // ---- compute: 2b x 4h microtile, scalar FFMA, 196 straight kk ----
    const int tx = tid & 7;            // h quad (x4 = 32 h)
    const int ty = tid >> 3;           // b pair (x2 = 64 b)

    float mu[2][4] = {}, qq[2][4] = {};
    const float* ap = &As[(ty * 2) * KCH];

    #pragma unroll 4
    for (int kk = 0; kk < KCH; kk++) {
        float a0 = ap[kk];
        float a1 = ap[KCH + kk];
        float4 b1 = *(const float4*)&B1s[kk * BPAD + tx * 4];
        float4 b2 = *(const float4*)&B2s[kk * BPAD + tx * 4];
        float q0 = a0 * a0, q1 = a1 * a1;
        mu[0][0] += a0 * b1.x; mu[0][1] += a0 * b1.y;
        mu[0][2] += a0 * b1.z; mu[0][3] += a0 * b1.w;
        mu[1][0] += a1 * b1.x; mu[1][1] += a1 * b1.y;
        mu[1][2] += a1 * b1.z; mu[1][3] += a1 * b1.w;
        qq[0][0] += q0 * b2.x; qq[0][1] += q0 * b2.y;
        qq[0][2] += q0 * b2.z; qq[0][3] += q0 * b2.w;
        qq[1][0] += q1 * b2.x; qq[1][1] += q1 * b2.y;
        qq[1][2] += q1 * b2.z; qq[1][3] += q1 * b2.w;
    }

    // ---- epilogue: split-K partials ----
    #pragma unroll
    for (int r = 0; r < 2; r++) {
        int b = b0 + ty * 2 + r;
        float4 m = make_float4(mu[r][0], mu[r][1], mu[r][2], mu[r][3]);
        float4 q = make_float4(qq[r][0], qq[r][1], qq[r][2], qq[r][3]);
        *(float4*)&g_pmu[(kc * BATCH + b) * DH + n0 + tx * 4] = m;
        *(float4*)&g_pq [(kc * BATCH + b) * DH + n0 + tx * 4] = q;
    }
}

// ---------------- s2 recompute from partials (cross-batch trace gather) ----------------
__device__ __forceinline__ float s2_at(int m, int h, const float* __restrict__ b_mu1) {
    float mu = b_mu1[h];
    #pragma unroll
    for (int c = 0; c < KC; c++) mu += g_pmu[(c * BATCH + m) * DH + h];
    if (mu <= 0.f) return 0.f;
    float q = g_spb1[h];
    #pragma unroll
    for (int c = 0; c < KC; c++) q += g_pq[(c * BATCH + m) * DH + h];
    return q;
}

// ---------------- per-warp accumulator strip over a 128-h quarter, float2 ----------------
template<int LO, int HI>
__device__ __forceinline__ void accum_strip(const float* __restrict__ m2s,
                                            const float* __restrict__ s2s,
                                            const float* __restrict__ w2s,
                                            float* __restrict__ wp,
                                            int h0, int lane) {
    float acc[HI - LO];
    #pragma unroll
    for (int j = 0; j < HI - LO; j++) acc[j] = 0.f;

    #pragma unroll
    for (int t = 0; t < 2; t++) {
        int h = h0 + t * 64 + lane * 2;
        float2 m = *(const float2*)&m2s[h];
        float2 s = *(const float2*)&s2s[h];
        float2 mm = make_float2(m.x * m.x, m.y * m.y);
        float2 w[DOUT], sw[DOUT];
        #pragma unroll
        for (int o = 0; o < DOUT; o++) w[o] = *(const float2*)&w2s[o * DH + h];
        #pragma unroll
        for (int o = 0; o < DOUT; o++) {
            sw[o].x = s.x * w[o].x;
            sw[o].y = s.y * w[o].y;
        }
        {
            int e = 0;
            #pragma unroll
            for (int o = 0; o < DOUT; o++)
                #pragma unroll
                for (int p = o; p < DOUT; p++) {
                    if (e >= LO && e < HI)
                        acc[e - LO] += w[p].x * sw[o].x + w[p].y * sw[o].y;
                    e++;
                }
        }
        #pragma unroll
        for (int o = 0; o < DOUT; o++)
            if (TRI_N + o >= LO && TRI_N + o < HI)
                acc[TRI_N + o - LO] += w[o].x * m.x + w[o].y * m.y;
        #pragma unroll
        for (int o = 0; o < DOUT; o++)
            if (65 + o >= LO && 65 + o < HI) {
                float2 ws = __ldg((const float2*)&g_Ws2[o * DH + h]);
                acc[65 + o - LO] += ws.x * mm.x + ws.y * mm.y;
            }
    }

    #pragma unroll
    for (int s = 16; s; s >>= 1)
        #pragma unroll
        for (int j = 0; j < HI - LO; j++)
            acc[j] += __shfl_xor_sync(0xffffffffu, acc[j], s);

    #pragma unroll
    for (int j = 0; j < HI - LO; j++)
        if (lane == j) wp[LO + j] = acc[j];
}

// ---------------- K2: one block per batch, 512 threads ----------------
__global__ __launch_bounds__(512) void k2_layer2(const float* __restrict__ b_mu1,
                                                 const float* __restrict__ b_mu2,
                                                 float* __restrict__ out) {
    __shared__ float m2s[DH], s2s[DH];
    __shared__ float w2s[DOUT * DH];
    __shared__ float wp[4][NACC];
    __shared__ float S[240];
    __shared__ float saq[DOUT];

    const int tid = threadIdx.x;
    const int warp = tid >> 5, lane = tid & 31;
    const int b = blockIdx.x;
    const int SZ = BATCH * DH;

    // ---- phase 1: combine split-K partials + bias + ReLU ----
    {
        int h = tid;
        int idx = b * DH + h;
        float mu = __ldg(b_mu1 + h);
        #pragma unroll
        for (int c = 0; c < KC; c++) mu += g_pmu[c * SZ + idx];
        float q = g_spb1[h];
        #pragma unroll
        for (int c = 0; c < KC; c++) q += g_pq[c * SZ + idx];
        bool gate = (mu > 0.f);
        m2s[h] = gate ? mu : 0.f;
        s2s[h] = gate ? q : 0.f;
    }
    for (int i = tid; i < DOUT * DH / 4; i += 512)
        *(float4*)&w2s[i * 4] = *(const float4*)&g_w2t[i * 4];
    __syncthreads();

    // ---- phase 2: 16 warps = 4 accumulator strips x 4 h-quarters ----
    {
        const int quarter = warp >> 2;
        const int h0 = quarter * 128;
        float* wpp = wp[quarter];
        switch (warp & 3) {
            case 0: accum_strip< 0, 19>(m2s, s2s, w2s, wpp, h0, lane); break;
            case 1: accum_strip<19, 38>(m2s, s2s, w2s, wpp, h0, lane); break;
            case 2: accum_strip<38, 57>(m2s, s2s, w2s, wpp, h0, lane); break;
            default: accum_strip<57, 75>(m2s, s2s, w2s, wpp, h0, lane); break;
        }
    }
    __syncthreads();

    // ---- assembly ----
    if (tid < NACC) {
        float v = (wp[0][tid] + wp[1][tid]) + (wp[2][tid] + wp[3][tid]);
        if (tid < TRI_N) {
            int o = 0, rem = tid;
            #pragma unroll
            for (int r = 0; r < DOUT; r++) {
                if (rem >= DOUT - r && o == r) { rem -= DOUT - r; o = r + 1; }
            }
            int p = o + rem;
            S[o * DOUT + p] = v;
            S[p * DOUT + o] = v;
        } else if (tid < 65) {
            int o = tid - TRI_N;
            S[210 + o] = v + __ldg(b_mu2 + o);
        } else {
            saq[tid - 65] = v;
        }
    }
    __syncthreads();
    if (tid < DOUT) {
        // faithful replication of reference's flattened-view trace term
        int n  = DOUT * b + tid;
        int qn = n >> 8;
        int mn = n & 255;
        float trf = g_Ws2[qn * DH + 2 * mn]     * s2_at(mn, mn, b_mu1)
                  + g_Ws2[qn * DH + 2 * mn + 1] * s2_at(mn, 256 + mn, b_mu1);
        S[tid * DOUT + tid] += trf + saq[tid] + g_spb2[tid];
    }
    __syncthreads();

    // ---- softmax + sandwich (warp 0) ----
    if (warp == 0) {
        float v = (lane < DOUT) ? S[210 + lane] : -FLT_MAX;
        float mx = v;
        #pragma unroll
        for (int s = 16; s; s >>= 1) mx = fmaxf(mx, __shfl_xor_sync(0xffffffffu, mx, s));
        float e = (lane < DOUT) ? expf(v - mx) : 0.f;
        float sm = e;
        #pragma unroll
        for (int s = 16; s; s >>= 1) sm += __shfl_xor_sync(0xffffffffu, sm, s);
        if (lane < DOUT) {
            float p = e / sm;
            S[200 + lane] = p;
            out[b * DOUT + lane] = p;
        }
        __syncwarp();

        if (lane < DOUT) {
            float a = 0.f;
            #pragma unroll
            for (int j = 0; j < DOUT; j++) a += S[200 + j] * S[j * DOUT + lane];
            S[220 + lane] = a;
        }
        __syncwarp();
        for (int e2 = lane; e2 < DOUT * DOUT; e2 += 32) {
            int i = e2 / DOUT, k = e2 % DOUT;
            S[100 + e2] = S[200 + i] * (S[e2] - S[220 + k]);
        }
        __syncwarp();
        if (lane < DOUT) {
            float a = 0.f;
            #pragma unroll
            for (int k = 0; k < DOUT; k++) a += S[100 + lane * DOUT + k] * S[200 + k];
            S[230 + lane] = a;
        }
        __syncwarp();
        for (int e2 = lane; e2 < DOUT * DOUT; e2 += 32) {
            int i = e2 / DOUT, l = e2 % DOUT;
            out[BATCH * DOUT + b * DOUT * DOUT + e2] = S[200 + l] * (S[100 + e2] - S[230 + i]);
        }
    }
}

// ---------------- K3: KL finalize ----------------
__global__ __launch_bounds__(64) void k3_fin(float* __restrict__ out) {
    __shared__ float kred[2];
    const int tid = threadIdx.x;
    float a = g_klpartA[tid];
    if (tid < 16) a += g_klpartB[tid];
    #pragma unroll
    for (int s = 16; s; s >>= 1) a += __shfl_xor_sync(0xffffffffu, a, s);
    if ((tid & 31) == 0) kred[tid >> 5] = a;
    __syncthreads();
    if (tid == 0)
        out[BATCH * DOUT + BATCH * DOUT * DOUT] =
            0.5f * ((kred[0] + kred[1]) - (float)(DH * DIN + DOUT * DH));
}

// ---------------- launch ----------------
extern "C" void kernel_launch(void* const* d_in, const int* in_sizes, int n_in,
                              void* d_out, int out_size) {
    const float* x        = (const float*)d_in[0];
    const float* w_mu1    = (const float*)d_in[1];
    const float* w_sigma1 = (const float*)d_in[2];
    const float* b_mu1    = (const float*)d_in[3];
    const float* b_sigma1 = (const float*)d_in[4];
    const float* w_mu2    = (const float*)d_in[5];
    const float* w_sigma2 = (const float*)d_in[6];
    const float* b_mu2    = (const float*)d_in[7];
    const float* b_sigma2 = (const float*)d_in[8];
    float* out = (float*)d_out;

    cudaFuncSetAttribute(k1_mega, cudaFuncAttributeMaxDynamicSharedMemorySize, SMEM_BYTES);
    k1_mega<<<TOTAL_BLOCKS, 256, SMEM_BYTES>>>(x, w_mu1, w_sigma1, b_sigma1,
                                               w_mu2, w_sigma2, b_sigma2);
    k2_layer2<<<BATCH, 512>>>(b_mu1, b_mu2, out);
    k3_fin<<<1, 64>>>(out);
}